// round 9
// baseline (speedup 1.0000x reference)
#include <cuda_runtime.h>
#include <cstddef>

// LoG = GaussianBlur(3,sigma=1) -> Laplacian(ksize=9) + 1, clip [0,255].
// Factorized: A(x)B(y)+B(x)A(y) = (P_x P_y) conv K3, where
//   P  = gauss3 (*) binom6   (9 taps, all positive)
//   K3 = [1,2,1](x)[1,-2,1] + [1,-2,1](x)[1,2,1] = [[2,0,2],[0,-8,0],[2,0,2]]
// Pipeline: horizontal P -> vertical P -> sparse 5-tap K3 combine (+1, clip).
// Reflect-101 pad of 5 on input == staged reflect pads (symmetric kernels).

#define Hn 512
#define Wn 512
#define ROWF 1536            // floats per image row (512*3)
#define TH 32
#define TWP 32
#define IN_H 42              // TH + 2*5
#define IN_WP 42
#define IN_PITCH 44          // 16B-aligned rows (deinterleaved channel planes)
#define IN_PLANE 1848        // 42*44
#define HP_PITCH 37          // hP row pitch (36 cols total, 34 used)
#define HP_PLANE 1554        // 42*37
#define QP 36                // q row pitch (34 cols used), even for float2
#define Q_PLANE 1240         // 34*36=1224 +16 pad
#define NTHREADS 512

__device__ __forceinline__ int reflect101(int i, int n) {
    i = (i < 0) ? -i : i;
    return (i >= n) ? (2 * n - 2 - i) : i;
}

__global__ __launch_bounds__(NTHREADS, 4)
void log_fused_kernel(const float* __restrict__ x, float* __restrict__ out) {
    extern __shared__ float smem[];
    float* in_s = smem;                        // 3 planes [42][44]
    float* hP_s = smem + 3 * IN_PLANE;         // 3 planes [42][HP_PITCH]
    float* q_s  = hP_s + 3 * HP_PLANE;         // 3 planes [34][QP]

    // P = gauss3 (*) [1,6,15,20,15,6,1]  (symmetric, sum = 64)
    const float P9[9] = {
        0.2740686191f,  2.0962744762f,  7.0962744762f, 13.9037255238f,
        17.2593138094f, 13.9037255238f, 7.0962744762f,  2.0962744762f,
        0.2740686191f };

    const int tid = threadIdx.x;
    const int h0  = blockIdx.y * TH;
    const int p0  = blockIdx.x * TWP;
    const size_t plane = (size_t)blockIdx.z * (size_t)(Hn * ROWF);
    const float* xp = x + plane;

    // ========= Phase 1: gmem -> smem (deinterleave, reflect-101) =============
    // Input tile: pixels p0-5 .. p0+36 (42), rows h0-5 .. h0+36 (42).
    if (p0 != 0 && p0 != (Wn - TWP)) {
        const int fidx0 = (p0 - 5) * 3 - 1;          // 16B-aligned start
        const int col4  = tid & 31;
        int r = tid >> 5;                            // 0..15

        int qq[4], cc[4];
        bool val[4];
        #pragma unroll
        for (int l = 0; l < 4; l++) {
            int off = 4 * col4 + l - 1;
            val[l] = (off >= 0) && (off < IN_WP * 3);
            int o = val[l] ? off : 0;
            qq[l] = o / 3;
            cc[l] = o - 3 * qq[l];
        }
        const float4* gp = (const float4*)(xp + fidx0 + 4 * col4);

        #pragma unroll
        for (int k = 0; k < 3; k++) {
            if (r < IN_H) {
                const int gh = reflect101(h0 - 5 + r, Hn);
                float4 v = gp[gh * (ROWF / 4)];
                float vv[4] = {v.x, v.y, v.z, v.w};
                const int rb = r * IN_PITCH;
                #pragma unroll
                for (int l = 0; l < 4; l++) {
                    if (val[l]) in_s[cc[l] * IN_PLANE + rb + qq[l]] = vv[l];
                }
            }
            r += 16;
        }
    } else {
        const int f  = tid & 127;
        const int rg = tid >> 7;                     // 0..3
        if (f < IN_WP * 3) {
            const int q = f / 3;
            const int c = f - q * 3;
            const int wp = reflect101(p0 - 5 + q, Wn);
            const int src_col = wp * 3 + c;
            float* dst = in_s + c * IN_PLANE + q;
            #pragma unroll 4
            for (int r = rg; r < IN_H; r += 4) {
                const int gh = reflect101(h0 - 5 + r, Hn);
                dst[r * IN_PITCH] = xp[(size_t)gh * ROWF + src_col];
            }
        }
    }
    __syncthreads();

    // ========= Phase 2: horizontal 9-tap P ===================================
    // hP col c (0..33 used) = pixel p0-1+c; hP(c) = sum_t P[t]*in[c+t].
    // 3 ch * 42 rows * 3 segments of 12 = 378 tasks; window 20 floats = 5xLDS.128.
    // Seg 2 touches padding cols 42,43 (garbage) -> only hP cols 34,35 (unused).
    if (tid < 378) {
        const int c   = tid / 126;
        const int rem = tid - c * 126;
        const int r   = rem / 3;
        const int seg = rem - r * 3;
        const float4* src4 = (const float4*)(in_s + c * IN_PLANE + r * IN_PITCH) + 3 * seg;

        float acc[12];
        #pragma unroll
        for (int j = 0; j < 12; j++) acc[j] = 0.f;

        #pragma unroll
        for (int k = 0; k < 5; k++) {
            float4 w = src4[k];
            float ws[4] = {w.x, w.y, w.z, w.w};
            #pragma unroll
            for (int u = 0; u < 4; u++) {
                const int i = 4 * k + u;
                const float v = ws[u];
                #pragma unroll
                for (int j = 0; j < 12; j++) {
                    const int t = i - j;
                    if (t >= 0 && t < 9)
                        acc[j] = fmaf(P9[t], v, acc[j]);
                }
            }
        }
        float* d = hP_s + c * HP_PLANE + r * HP_PITCH + 12 * seg;
        #pragma unroll
        for (int j = 0; j < 12; j++) d[j] = acc[j];
    }
    __syncthreads();

    // ========= Phase 3: vertical 9-tap P =====================================
    // q row qr (0..33) = image row h0-1+qr; q(qr,c) = sum_t P[t]*hP(qr+t, c).
    // 34 cols * 3 ch = 102 columns * 3 chunks of 12 rows {0,11,22} = 306 tasks.
    if (tid < 306) {
        const int m     = tid % 102;
        const int chunk = tid / 102;
        const int col = m % 34;
        const int ch  = m / 34;
        const int r0  = 11 * chunk;
        const float* s = hP_s + ch * HP_PLANE + r0 * HP_PITCH + col;

        float acc[12];
        #pragma unroll
        for (int j = 0; j < 12; j++) acc[j] = 0.f;

        #pragma unroll
        for (int i = 0; i < 20; i++) {
            const float v = s[i * HP_PITCH];
            #pragma unroll
            for (int j = 0; j < 12; j++) {
                const int t = i - j;
                if (t >= 0 && t < 9)
                    acc[j] = fmaf(P9[t], v, acc[j]);
            }
        }
        float* d = q_s + ch * Q_PLANE + r0 * QP + col;
        #pragma unroll
        for (int j = 0; j < 12; j++) d[j * QP] = acc[j];
    }
    __syncthreads();

    // ========= Phase 4: sparse K3 combine + delta + clip =====================
    // out(r,p) = 2*(q[r][p]+q[r][p+2]+q[r+2][p]+q[r+2][p+2]) - 8*q[r+1][p+1] + 1
    // 16 pixel-pairs * 3 ch = 48 columns * 4 chunks of 8 rows = 192 tasks.
    // Each: 10 rows x 2 float2 loads cover q cols 2pp..2pp+3.
    if (tid < 192) {
        const int m     = tid % 48;
        const int chunk = tid / 48;
        const int ch = m % 3;
        const int pp = m / 3;                        // pixel pair 0..15
        const int r0 = 8 * chunk;
        const float2* b = (const float2*)(q_s + ch * Q_PLANE + r0 * QP) + pp;

        float a0[8], a1[8];
        #pragma unroll
        for (int j = 0; j < 8; j++) { a0[j] = 1.0f; a1[j] = 1.0f; }

        #pragma unroll
        for (int i = 0; i < 10; i++) {
            const float2 v01 = b[i * (QP / 2)];
            const float2 v23 = b[i * (QP / 2) + 1];
            const float t0 = v01.x + v23.x;
            const float t1 = v01.y + v23.y;
            if (i < 8) {
                a0[i] = fmaf(2.0f, t0, a0[i]);
                a1[i] = fmaf(2.0f, t1, a1[i]);
            }
            if (i >= 2) {
                a0[i - 2] = fmaf(2.0f, t0, a0[i - 2]);
                a1[i - 2] = fmaf(2.0f, t1, a1[i - 2]);
            }
            if (i >= 1 && i <= 8) {
                a0[i - 1] = fmaf(-8.0f, v01.y, a0[i - 1]);
                a1[i - 1] = fmaf(-8.0f, v23.x, a1[i - 1]);
            }
        }
        float* op = out + plane + (size_t)(h0 + r0) * ROWF + (p0 + 2 * pp) * 3 + ch;
        #pragma unroll
        for (int j = 0; j < 8; j++) {
            op[j * ROWF]     = fminf(fmaxf(a0[j], 0.0f), 255.0f);
            op[j * ROWF + 3] = fminf(fmaxf(a1[j], 0.0f), 255.0f);
        }
    }
}

extern "C" void kernel_launch(void* const* d_in, const int* in_sizes, int n_in,
                              void* d_out, int out_size) {
    const float* x = (const float*)d_in[0];
    float* out = (float*)d_out;
    const int N = in_sizes[0] / (Hn * Wn * 3);

    const int smem_bytes =
        (3 * IN_PLANE + 3 * HP_PLANE + 3 * Q_PLANE) * (int)sizeof(float);
    cudaFuncSetAttribute(log_fused_kernel,
                         cudaFuncAttributeMaxDynamicSharedMemorySize, smem_bytes);

    dim3 grid(Wn / TWP, Hn / TH, N);   // (16, 16, N)
    log_fused_kernel<<<grid, NTHREADS, smem_bytes>>>(x, out);
}

// round 10
// speedup vs baseline: 1.3198x; 1.3198x over previous
#include <cuda_runtime.h>
#include <cstddef>

// LoG = GaussianBlur(3,sigma=1) -> Laplacian(ksize=9) + 1, clip [0,255].
// Fused: composite 11x11 = A(x)B(y) + B(x)A(y), A = g3*S9 = P9*[1,2,1],
// B = g3*D2_9 = P9*[1,-2,1], P9 = g3*binom6. Phase 2 computes hP (9-tap) once
// and derives U = [1,2,1]*hP, W = [1,-2,1]*hP; then out = B(y)*U + A(y)*W.
// Reflect-101 pad of 5 on input == staged reflect pads (symmetric kernels).

#define Hn 512
#define Wn 512
#define ROWF 1536            // floats per image row (512*3)
#define TH 32
#define TWP 32
#define HALO 5
#define IN_H 42
#define IN_WP 42
#define IN_PITCH 44          // 16B-aligned rows (deinterleaved channel planes)
#define IN_PLANE 1848        // 42*44
#define HPP 66               // (U,W) float2 row pitch = 33 (odd -> perfect STS banks)
#define HAB_PLANE 2774       // 42*66=2772 +2; /2 = 1387 == 11 mod 16 -> perfect LDS banks
#define NTHREADS 512

__device__ __forceinline__ int reflect101(int i, int n) {
    i = (i < 0) ? -i : i;
    return (i >= n) ? (2 * n - 2 - i) : i;
}

__global__ __launch_bounds__(NTHREADS, 4)
void log_fused_kernel(const float* __restrict__ x, float* __restrict__ out) {
    extern __shared__ float smem[];
    float* in_s  = smem;                       // 3 planes [IN_H][IN_PITCH]
    float* hAB_s = smem + 3 * IN_PLANE;        // 3 planes [IN_H][33 float2] (U,W)

    // 11-tap composites (used in vertical pass)
    const float cA[11] = {
        0.274068619061f,  2.644411714f, 11.562892048f, 30.192548953f,
        52.163039333f,   62.326078667f, 52.163039333f, 30.192548953f,
        11.562892048f,    2.644411714f,  0.274068619061f };
    const float cB[11] = {
        0.274068619061f,  1.548137238f,  3.177794143f,  1.807451048f,
       -3.451862762f,    -6.711176571f, -3.451862762f,  1.807451048f,
        3.177794143f,     1.548137238f,  0.274068619061f };
    // 9-tap shared factor P9 = gauss3 (*) [1,6,15,20,15,6,1]
    const float P9[9] = {
        0.2740686191f,  2.0962744762f,  7.0962744762f, 13.9037255238f,
        17.2593138094f, 13.9037255238f, 7.0962744762f,  2.0962744762f,
        0.2740686191f };

    const int tid = threadIdx.x;
    const int h0  = blockIdx.y * TH;
    const int p0  = blockIdx.x * TWP;
    const size_t plane = (size_t)blockIdx.z * (size_t)(Hn * ROWF);
    const float* xp = x + plane;

    // ================= Phase 1: gmem -> smem (deinterleave, reflect-101) ======
    if (p0 != 0 && p0 != (Wn - TWP)) {
        // interior-W fast path: float4 loads, no column reflect math
        const int fidx0 = (p0 - HALO) * 3 - 1;       // 16B-aligned start
        const int col4  = tid & 31;
        int r = tid >> 5;                            // 0..15

        int qq[4], cc[4];
        bool val[4];
        #pragma unroll
        for (int l = 0; l < 4; l++) {
            int off = 4 * col4 + l - 1;
            val[l] = (off >= 0) && (off < IN_WP * 3);
            int o = val[l] ? off : 0;
            qq[l] = o / 3;
            cc[l] = o - 3 * qq[l];
        }
        const float4* gp = (const float4*)(xp + fidx0 + 4 * col4);

        #pragma unroll
        for (int k = 0; k < 3; k++) {
            if (r < IN_H) {
                const int gh = reflect101(h0 - HALO + r, Hn);
                float4 v = gp[gh * (ROWF / 4)];
                float vv[4] = {v.x, v.y, v.z, v.w};
                const int rb = r * IN_PITCH;
                #pragma unroll
                for (int l = 0; l < 4; l++) {
                    if (val[l]) in_s[cc[l] * IN_PLANE + rb + qq[l]] = vv[l];
                }
            }
            r += 16;
        }
    } else {
        // border-W scalar path (reflect both dims)
        const int f  = tid & 127;
        const int rg = tid >> 7;                     // 0..3
        if (f < IN_WP * 3) {
            const int q = f / 3;
            const int c = f - q * 3;
            const int wp = reflect101(p0 - HALO + q, Wn);
            const int src_col = wp * 3 + c;
            float* dst = in_s + c * IN_PLANE + q;
            #pragma unroll 4
            for (int r = rg; r < IN_H; r += 4) {
                const int gh = reflect101(h0 - HALO + r, Hn);
                dst[r * IN_PITCH] = xp[(size_t)gh * ROWF + src_col];
            }
        }
    }
    __syncthreads();

    // ========== Phase 2: horizontal 9-tap hP, then derive (U,W) ==============
    // 3 ch * 42 rows * 4 eight-output segments = 504 tasks, one per thread.
    // Same 18-float window as before: 4x LDS.128 + 1x LDS.64.
    // hP[m] (m=0..9) covers pixel positions p-1..p+8; U/W from 3 neighbors.
    if (tid < 504) {
        const int c   = tid / (IN_H * 4);
        const int rem = tid - c * (IN_H * 4);
        const int r   = rem >> 2;
        const int p   = (rem & 3) << 3;
        const float* src = in_s + c * IN_PLANE + r * IN_PITCH + p;

        float hP[10];
        #pragma unroll
        for (int m = 0; m < 10; m++) hP[m] = 0.f;

        #pragma unroll
        for (int ib = 0; ib < 4; ib++) {
            float4 v4 = *(const float4*)(src + 4 * ib);
            float vs[4] = {v4.x, v4.y, v4.z, v4.w};
            #pragma unroll
            for (int s = 0; s < 4; s++) {
                const int i = 4 * ib + s;
                const float v = vs[s];
                #pragma unroll
                for (int m = 0; m < 10; m++) {
                    const int t = i - m;
                    if (t >= 0 && t < 9)
                        hP[m] = fmaf(P9[t], v, hP[m]);
                }
            }
        }
        {
            float2 v2 = *(const float2*)(src + 16);
            float vs[2] = {v2.x, v2.y};
            #pragma unroll
            for (int s = 0; s < 2; s++) {
                const int i = 16 + s;
                const float v = vs[s];
                #pragma unroll
                for (int m = 0; m < 10; m++) {
                    const int t = i - m;
                    if (t >= 0 && t < 9)
                        hP[m] = fmaf(P9[t], v, hP[m]);
                }
            }
        }

        // U = hP[j] + 2 hP[j+1] + hP[j+2]; W = hP[j] - 2 hP[j+1] + hP[j+2]
        float2* d = (float2*)(hAB_s + c * HAB_PLANE + r * HPP) + p;
        #pragma unroll
        for (int j = 0; j < 8; j++) {
            const float s2 = hP[j] + hP[j + 2];
            const float U  = fmaf(2.0f, hP[j + 1], s2);
            const float W  = fmaf(-2.0f, hP[j + 1], s2);
            d[j] = make_float2(U, W);
        }
    }
    __syncthreads();

    // ========== Phase 3: vertical 11-tap combine, 16-row chunks ==============
    // out = sum_t cB[t]*U(r+t) + cA[t]*W(r+t)  (+1, clip).
    // 96 output columns (32 px * 3 ch) * 2 chunks of 16 rows = 192 tasks.
    if (tid < 192) {
        const int col   = tid % 96;       // consecutive tid -> consecutive floats
        const int chunk = tid / 96;
        const int p = col / 3;
        const int c = col - p * 3;
        const int r0 = chunk * 16;
        const float2* s = (const float2*)(hAB_s + c * HAB_PLANE) + r0 * (HPP / 2) + p;

        float acc[16];
        #pragma unroll
        for (int j = 0; j < 16; j++) acc[j] = 1.0f;   // delta = 1

        #pragma unroll
        for (int i = 0; i < 26; i++) {
            const float2 v = s[i * (HPP / 2)];        // (U, W)
            #pragma unroll
            for (int j = 0; j < 16; j++) {
                const int t = i - j;
                if (t >= 0 && t < 11) {
                    acc[j] = fmaf(cB[t], v.x, acc[j]);
                    acc[j] = fmaf(cA[t], v.y, acc[j]);
                }
            }
        }
        float* op = out + plane + (size_t)(h0 + r0) * ROWF + p0 * 3 + col;
        #pragma unroll
        for (int j = 0; j < 16; j++) {
            op[j * ROWF] = fminf(fmaxf(acc[j], 0.0f), 255.0f);
        }
    }
}

extern "C" void kernel_launch(void* const* d_in, const int* in_sizes, int n_in,
                              void* d_out, int out_size) {
    const float* x = (const float*)d_in[0];
    float* out = (float*)d_out;
    const int N = in_sizes[0] / (Hn * Wn * 3);

    const int smem_bytes = (3 * IN_PLANE + 3 * HAB_PLANE) * (int)sizeof(float);
    cudaFuncSetAttribute(log_fused_kernel,
                         cudaFuncAttributeMaxDynamicSharedMemorySize, smem_bytes);

    dim3 grid(Wn / TWP, Hn / TH, N);   // (16, 16, N)
    log_fused_kernel<<<grid, NTHREADS, smem_bytes>>>(x, out);
}